// round 3
// baseline (speedup 1.0000x reference)
#include <cuda_runtime.h>
#include <cstdint>

#define BATCH    8192
#define ENT_DIM  64
#define GRID_G   16
#define EMB_DIM  1024      // ENT_DIM * GRID_G
#define N_REL    5000
#define LN_EPS   1e-5f
#define NTHREADS 256
#define PER_THR  4         // EMB_DIM / NTHREADS
#define SCAN_T   1024
#define SCAN_C   5         // ceil(N_REL / SCAN_T)

// ---- device scratch (no allocations allowed) ----
__device__ int g_ids_is64;
__device__ int g_hist[N_REL];
__device__ int g_start[N_REL + 1];
__device__ int g_cursor[N_REL];
__device__ int g_perm[BATCH];

// ---------------------------------------------------------------------------
// 1) int64 vs int32 id dtype detection (reference declares int64; jax without
//    x64 silently emits int32). If data is int32, interpreting 8 bytes as
//    int64 packs two random ids -> >= 2^32 almost surely.
__global__ void detect_ids_kernel(const void* __restrict__ ids) {
    __shared__ int ok[64];
    const long long* p = (const long long*)ids;
    long long v = p[threadIdx.x];
    ok[threadIdx.x] = (v >= 0 && v < N_REL) ? 1 : 0;
    __syncthreads();
    if (threadIdx.x == 0) {
        int all = 1;
        #pragma unroll
        for (int i = 0; i < 64; i++) all &= ok[i];
        g_ids_is64 = all;
    }
}

__device__ __forceinline__ int load_id(const void* ids, int b, int is64) {
    if (is64) return (int)((const long long*)ids)[b];
    return ((const int*)ids)[b];
}

// 2) zero histogram
__global__ void zero_hist_kernel() {
    int i = blockIdx.x * blockDim.x + threadIdx.x;
    if (i < N_REL) g_hist[i] = 0;
}

// 3) histogram of relation ids
__global__ void hist_kernel(const void* __restrict__ ids) {
    int b = blockIdx.x * blockDim.x + threadIdx.x;
    if (b < BATCH) {
        int r = load_id(ids, b, g_ids_is64);
        atomicAdd(&g_hist[r], 1);
    }
}

// 4) single-block exclusive scan of 5000 bins -> g_start / g_cursor
__global__ __launch_bounds__(SCAN_T) void scan_kernel() {
    __shared__ int s[SCAN_T];
    const int i = threadIdx.x;
    int local[SCAN_C];
    int sum = 0;
    #pragma unroll
    for (int q = 0; q < SCAN_C; q++) {
        int bin = i * SCAN_C + q;
        local[q] = (bin < N_REL) ? g_hist[bin] : 0;
        sum += local[q];
    }
    s[i] = sum;
    __syncthreads();
    // Hillis–Steele inclusive scan
    for (int off = 1; off < SCAN_T; off <<= 1) {
        int v = (i >= off) ? s[i - off] : 0;
        __syncthreads();
        s[i] += v;
        __syncthreads();
    }
    int excl = s[i] - sum;
    #pragma unroll
    for (int q = 0; q < SCAN_C; q++) {
        int bin = i * SCAN_C + q;
        if (bin < N_REL) {
            g_start[bin]  = excl;
            g_cursor[bin] = excl;
            excl += local[q];
        }
    }
    if (i == SCAN_T - 1) g_start[N_REL] = s[SCAN_T - 1];
}

// 5) scatter rows into id-sorted permutation
__global__ void scatter_kernel(const void* __restrict__ ids) {
    int b = blockIdx.x * blockDim.x + threadIdx.x;
    if (b < BATCH) {
        int r = load_id(ids, b, g_ids_is64);
        int pos = atomicAdd(&g_cursor[r], 1);
        g_perm[pos] = b;
    }
}

// ---------------------------------------------------------------------------
// 6) main kernel: one CTA per relation id; T held in registers across all
//    rows of the group -> each unique relation's 64KB crosses DRAM/L2/L1
//    exactly once.
__global__ __launch_bounds__(NTHREADS, 2)
void proj_ln_grouped_kernel(const float* __restrict__ ent_emb,
                            const float* __restrict__ rel_tran,
                            const float* __restrict__ rel_bias,
                            const float* __restrict__ ln_w,
                            const float* __restrict__ ln_b,
                            float* __restrict__ out)
{
    const int id = blockIdx.x;
    const int s0 = g_start[id];
    const int s1 = g_start[id + 1];
    if (s0 >= s1) return;

    const int t = threadIdx.x;

    __shared__ float se[EMB_DIM];
    __shared__ float red_s[NTHREADS / 32];
    __shared__ float red_ss[NTHREADS / 32];
    __shared__ float s_mu, s_rstd;

    const float* T  = rel_tran + (size_t)id * (ENT_DIM * GRID_G * GRID_G);
    const float* Bm = rel_bias + (size_t)id * (ENT_DIM * GRID_G);

    // Load this relation's transform slice + bias + LN params into registers.
    // 16 x LDG.128 + 12 x LDG.32 per thread, all independent -> high MLP.
    float4 a[PER_THR][4];
    float  bias[PER_THR], lw[PER_THR], lb[PER_THR];
    #pragma unroll
    for (int k = 0; k < PER_THR; k++) {
        const int j = t + k * NTHREADS;           // output index in [0,1024)
        const float4* Trow = (const float4*)(T + (size_t)j * GRID_G);
        #pragma unroll
        for (int q = 0; q < 4; q++) a[k][q] = Trow[q];
        bias[k] = Bm[j];
        lw[k]   = ln_w[j];
        lb[k]   = ln_b[j];
    }

    const int lane = t & 31;
    const int wid  = t >> 5;

    for (int s = s0; s < s1; s++) {
        const int b = g_perm[s];

        __syncthreads();   // previous iteration's readers of se are done
        ((float4*)se)[t] = ((const float4*)(ent_emb + (size_t)b * EMB_DIM))[t];
        __syncthreads();

        float x[PER_THR];
        float sum = 0.f, sumsq = 0.f;
        #pragma unroll
        for (int k = 0; k < PER_THR; k++) {
            const int j = t + k * NTHREADS;
            const int d = j >> 4;
            const float4* ed = (const float4*)(se + d * GRID_G);
            float acc = bias[k];
            #pragma unroll
            for (int q = 0; q < 4; q++) {
                float4 av = a[k][q];
                float4 ev = ed[q];
                acc += av.x * ev.x + av.y * ev.y + av.z * ev.z + av.w * ev.w;
            }
            x[k] = acc;
            sum += acc;
            sumsq += acc * acc;
        }

        #pragma unroll
        for (int o = 16; o > 0; o >>= 1) {
            sum   += __shfl_xor_sync(0xFFFFFFFFu, sum,   o);
            sumsq += __shfl_xor_sync(0xFFFFFFFFu, sumsq, o);
        }
        if (lane == 0) { red_s[wid] = sum; red_ss[wid] = sumsq; }
        __syncthreads();
        if (t == 0) {
            float ssm = 0.f, sss = 0.f;
            #pragma unroll
            for (int i = 0; i < NTHREADS / 32; i++) { ssm += red_s[i]; sss += red_ss[i]; }
            const float inv_n = 1.0f / (float)EMB_DIM;
            const float mu = ssm * inv_n;
            const float var = sss * inv_n - mu * mu;
            s_mu = mu;
            s_rstd = rsqrtf(var + LN_EPS);
        }
        __syncthreads();
        const float mu   = s_mu;
        const float rstd = s_rstd;

        float* o = out + (size_t)b * EMB_DIM;
        #pragma unroll
        for (int k = 0; k < PER_THR; k++) {
            const int j = t + k * NTHREADS;
            o[j] = (x[k] - mu) * rstd * lw[k] + lb[k];
        }
    }
}

extern "C" void kernel_launch(void* const* d_in, const int* in_sizes, int n_in,
                              void* d_out, int out_size) {
    const float* ent_emb  = (const float*)d_in[0];
    const void*  proj_ids = d_in[1];
    const float* rel_tran = (const float*)d_in[2];
    const float* rel_bias = (const float*)d_in[3];
    const float* ln_w     = (const float*)d_in[4];
    const float* ln_b     = (const float*)d_in[5];
    float* out = (float*)d_out;

    detect_ids_kernel<<<1, 64>>>(proj_ids);
    zero_hist_kernel<<<(N_REL + 255) / 256, 256>>>();
    hist_kernel<<<(BATCH + 255) / 256, 256>>>(proj_ids);
    scan_kernel<<<1, SCAN_T>>>();
    scatter_kernel<<<(BATCH + 255) / 256, 256>>>(proj_ids);
    proj_ln_grouped_kernel<<<N_REL, NTHREADS>>>(ent_emb, rel_tran, rel_bias,
                                                ln_w, ln_b, out);
}